// round 16
// baseline (speedup 1.0000x reference)
#include <cuda_runtime.h>
#include <cuda_fp16.h>
#include <cstdint>

// Attention O = softmax(QK^T)V, [B=4,H=16,S=2048,D=64], fp32.
// R14: 5 CTAs/SM (128 thr, 20 warps/SM) via SW128-swizzled smem (no padding)
//      + temporal key-half split (s[16] live -> regs <= 102).
//      K double-buffered, V single-buffered cp.async. 2-pass QK^T, fp16 PV.

#define S_LEN 2048
#define DHD 64
#define BM 64
#define BN 64
#define NT (S_LEN / BN)     // 32
#define TOTE (64LL * S_LEN * DHD)
#define LOG2E 1.44269504088896340736f

// byte offsets inside the 128B-aligned smem arena (swizzled 128B rows)
#define OB_QH 0
#define OB_QL 8192
#define OB_K0 16384
#define OB_K1 24576
#define OB_V  32768
#define SMEM_BYTES (40960 + 128)

#define SWZ(b) ((b) ^ (((b) >> 3) & 0x70u))

__device__ __half g_KH[TOTE];
__device__ __half g_VS[TOTE];

static __device__ __forceinline__ uint32_t sa(const void* p) {
    uint32_t a;
    asm("{\n\t.reg .u64 t;\n\tcvta.to.shared.u64 t, %1;\n\tcvt.u32.u64 %0, t;\n\t}"
        : "=r"(a) : "l"(p));
    return a;
}
static __device__ __forceinline__ float ex2(float x) {
    float r;
    asm("ex2.approx.f32 %0, %1;" : "=f"(r) : "f"(x));
    return r;
}
static __device__ __forceinline__ void ldx4(uint32_t* r, uint32_t a) {
    asm volatile("ldmatrix.sync.aligned.m8n8.x4.shared.b16 {%0,%1,%2,%3}, [%4];"
                 : "=r"(r[0]), "=r"(r[1]), "=r"(r[2]), "=r"(r[3]) : "r"(a));
}
static __device__ __forceinline__ void ldx4t(uint32_t* r, uint32_t a) {
    asm volatile("ldmatrix.sync.aligned.m8n8.x4.trans.shared.b16 {%0,%1,%2,%3}, [%4];"
                 : "=r"(r[0]), "=r"(r[1]), "=r"(r[2]), "=r"(r[3]) : "r"(a));
}
static __device__ __forceinline__ void mma16816(float* d, const uint32_t* a, const uint32_t* b) {
    asm volatile("mma.sync.aligned.m16n8k16.row.col.f32.f16.f16.f32 "
                 "{%0,%1,%2,%3},{%4,%5,%6,%7},{%8,%9},{%0,%1,%2,%3};"
                 : "+f"(d[0]), "+f"(d[1]), "+f"(d[2]), "+f"(d[3])
                 : "r"(a[0]), "r"(a[1]), "r"(a[2]), "r"(a[3]), "r"(b[0]), "r"(b[1]));
}
static __device__ __forceinline__ void cpasync16(uint32_t dst, const void* src) {
    asm volatile("cp.async.cg.shared.global [%0], [%1], 16;" :: "r"(dst), "l"(src) : "memory");
}
#define CP_COMMIT() asm volatile("cp.async.commit_group;" ::: "memory")
#define CP_WAIT0()  asm volatile("cp.async.wait_group 0;" ::: "memory")
#define CP_WAIT1()  asm volatile("cp.async.wait_group 1;" ::: "memory")

static __device__ __forceinline__ void split2(float a, float b, uint32_t& hi, uint32_t& lo) {
    __half ha = __float2half_rn(a), hb = __float2half_rn(b);
    __half2 h = __halves2half2(ha, hb);
    __half2 l = __floats2half2_rn(a - __half2float(ha), b - __half2float(hb));
    hi = *(uint32_t*)&h;
    lo = *(uint32_t*)&l;
}

// ---- pass 1: K,V fp32 -> fp16 scratch ----
__global__ void __launch_bounds__(256)
preconv_kernel(const float* __restrict__ K, const float* __restrict__ V) {
    const long long gid = (long long)blockIdx.x * 256 + threadIdx.x;
    const long long HALF = TOTE / 2;
    long long ia = gid * 4;
    long long ib = ia + HALF;
    if (ib >= TOTE) return;
    float4 ka = *(const float4*)(K + ia);
    float4 va = *(const float4*)(V + ia);
    float4 kb = *(const float4*)(K + ib);
    float4 vb = *(const float4*)(V + ib);
    __half2 t0 = __floats2half2_rn(ka.x, ka.y), t1 = __floats2half2_rn(ka.z, ka.w);
    *(uint32_t*)(g_KH + ia) = *(uint32_t*)&t0; *(uint32_t*)(g_KH + ia + 2) = *(uint32_t*)&t1;
    t0 = __floats2half2_rn(va.x, va.y); t1 = __floats2half2_rn(va.z, va.w);
    *(uint32_t*)(g_VS + ia) = *(uint32_t*)&t0; *(uint32_t*)(g_VS + ia + 2) = *(uint32_t*)&t1;
    t0 = __floats2half2_rn(kb.x, kb.y); t1 = __floats2half2_rn(kb.z, kb.w);
    *(uint32_t*)(g_KH + ib) = *(uint32_t*)&t0; *(uint32_t*)(g_KH + ib + 2) = *(uint32_t*)&t1;
    t0 = __floats2half2_rn(vb.x, vb.y); t1 = __floats2half2_rn(vb.z, vb.w);
    *(uint32_t*)(g_VS + ib) = *(uint32_t*)&t0; *(uint32_t*)(g_VS + ib + 2) = *(uint32_t*)&t1;
}

// ---- pass 2: flash attention, 128 thr, 5 CTAs/SM target ----
__global__ void __launch_bounds__(128, 5)
attn_mma_kernel(const float* __restrict__ Q, float* __restrict__ Out)
{
    extern __shared__ char smc[];
    const uint32_t sbr = sa(smc);
    const uint32_t sb = (sbr + 127u) & ~127u;
    char* smb = smc + (sb - sbr);

    const int tid  = threadIdx.x;
    const int wid  = tid >> 5;
    const int lane = tid & 31;
    const int l15  = lane & 15;

    const long long base = (long long)blockIdx.y * (S_LEN * DHD);
    const float*  Qg  = Q + base + (long long)blockIdx.x * (BM * DHD);
    const __half* KHg = g_KH + base;
    const __half* VSg = g_VS + base;
    float*        Og  = Out + base + (long long)blockIdx.x * (BM * DHD);

    // cp.async chunk map: 512 chunks of 16B per 64x128B tile, 4 per thread
    int crow[4], ccg[4];
    #pragma unroll
    for (int j = 0; j < 4; j++) {
        int idx = tid + j * 128;
        crow[j] = idx >> 3;
        ccg[j]  = (idx & 7) * 8;      // halfs (16B)
    }

    // ---- prologue: K(0) -> K0 ----
    #pragma unroll
    for (int j = 0; j < 4; j++)
        cpasync16(sb + OB_K0 + SWZ((uint32_t)(crow[j] * 128 + ccg[j] * 2)),
                  KHg + crow[j] * DHD + ccg[j]);
    CP_COMMIT();

    // ---- Q: load, *log2e, hi/lo split -> swizzled smem ----
    #pragma unroll
    for (int i = 0; i < 8; i++) {
        int idx = tid * 4 + i * 512;
        int r = idx >> 6, c = idx & 63;
        float4 q = *(const float4*)(Qg + r * DHD + c);
        q.x *= LOG2E; q.y *= LOG2E; q.z *= LOG2E; q.w *= LOG2E;
        uint32_t h0, l0, h1, l1;
        split2(q.x, q.y, h0, l0);
        split2(q.z, q.w, h1, l1);
        uint32_t b = SWZ((uint32_t)(r * 128 + c * 2));
        *(uint2*)(smb + OB_QH + b) = make_uint2(h0, h1);
        *(uint2*)(smb + OB_QL + b) = make_uint2(l0, l1);
    }

    float o[8][4];
    #pragma unroll
    for (int nn = 0; nn < 8; nn++)
        #pragma unroll
        for (int j = 0; j < 4; j++) o[nn][j] = 0.0f;
    float m_lo = -1.0e30f, m_hi = -1.0e30f, l_lo = 0.0f, l_hi = 0.0f;

    for (int t = 0; t < NT; t++) {
        CP_WAIT0();            // K(t) (and all older) landed
        __syncthreads();       // collective visibility; V/K buffer reuse safe

        // issue V(t) (single buffer; V(t-1) reads finished before barrier)
        {
            const long long kg = (long long)t * BN * DHD;
            #pragma unroll
            for (int j = 0; j < 4; j++)
                cpasync16(sb + OB_V + SWZ((uint32_t)(crow[j] * 128 + ccg[j] * 2)),
                          VSg + kg + crow[j] * DHD + ccg[j]);
            CP_COMMIT();
        }
        // issue K(t+1) into the other K buffer (full-tile window)
        if (t + 1 < NT) {
            const long long kg = (long long)(t + 1) * BN * DHD;
            uint32_t kb = sb + (((t + 1) & 1) ? OB_K1 : OB_K0);
            #pragma unroll
            for (int j = 0; j < 4; j++)
                cpasync16(kb + SWZ((uint32_t)(crow[j] * 128 + ccg[j] * 2)),
                          KHg + kg + crow[j] * DHD + ccg[j]);
        }
        CP_COMMIT();           // always commit (possibly empty) for wait bookkeeping

        const uint32_t kbuf = sb + ((t & 1) ? OB_K1 : OB_K0);

        // ==== two key-halves: QK(h) -> softmax(h) -> PV(h) ====
        #pragma unroll
        for (int h = 0; h < 2; h++) {
            // ---- QK^T half: 32 keys, 2-pass (Qh+Ql vs Kh) ----
            float s[4][4];
            #pragma unroll
            for (int q = 0; q < 4; q++)
                #pragma unroll
                for (int j = 0; j < 4; j++) s[q][j] = 0.0f;

            #pragma unroll
            for (int kk = 0; kk < 4; kk++) {
                const int ar = wid * 16 + (lane & 7) + ((lane >> 3) & 1) * 8;
                const int ac = kk * 16 + (lane >> 4) * 8;
                uint32_t qb = SWZ((uint32_t)(ar * 128 + ac * 2));
                uint32_t ah[4], al[4];
                ldx4(ah, sb + OB_QH + qb);
                ldx4(al, sb + OB_QL + qb);
                const int kr = (lane & 7) + ((lane >> 4) & 1) * 8;
                const int kc = kk * 16 + ((lane >> 3) & 1) * 8;
                #pragma unroll
                for (int n2 = 0; n2 < 2; n2++) {
                    int row = h * 32 + n2 * 16 + kr;
                    uint32_t bh4[4];
                    ldx4(bh4, kbuf + SWZ((uint32_t)(row * 128 + kc * 2)));
                    mma16816(s[2 * n2],     ah, bh4);
                    mma16816(s[2 * n2],     al, bh4);
                    mma16816(s[2 * n2 + 1], ah, bh4 + 2);
                    mma16816(s[2 * n2 + 1], al, bh4 + 2);
                }
            }

            // ---- online softmax for this half ----
            float mt_lo = -1.0e30f, mt_hi = -1.0e30f;
            #pragma unroll
            for (int q = 0; q < 4; q++) {
                mt_lo = fmaxf(mt_lo, fmaxf(s[q][0], s[q][1]));
                mt_hi = fmaxf(mt_hi, fmaxf(s[q][2], s[q][3]));
            }
            mt_lo = fmaxf(mt_lo, __shfl_xor_sync(0xffffffffu, mt_lo, 1));
            mt_lo = fmaxf(mt_lo, __shfl_xor_sync(0xffffffffu, mt_lo, 2));
            mt_hi = fmaxf(mt_hi, __shfl_xor_sync(0xffffffffu, mt_hi, 1));
            mt_hi = fmaxf(mt_hi, __shfl_xor_sync(0xffffffffu, mt_hi, 2));

            const float mn_lo = fmaxf(m_lo, mt_lo);
            const float mn_hi = fmaxf(m_hi, mt_hi);
            const float sc_lo = ex2(m_lo - mn_lo);
            const float sc_hi = ex2(m_hi - mn_hi);
            m_lo = mn_lo; m_hi = mn_hi;
            l_lo *= sc_lo; l_hi *= sc_hi;
            #pragma unroll
            for (int nn = 0; nn < 8; nn++) {
                o[nn][0] *= sc_lo; o[nn][1] *= sc_lo;
                o[nn][2] *= sc_hi; o[nn][3] *= sc_hi;
            }

            uint32_t pa[4], pb[4];
            #pragma unroll
            for (int q = 0; q < 4; q++) {
                float p0 = ex2(s[q][0] - mn_lo);
                float p1 = ex2(s[q][1] - mn_lo);
                float p2 = ex2(s[q][2] - mn_hi);
                float p3 = ex2(s[q][3] - mn_hi);
                l_lo += p0 + p1;
                l_hi += p2 + p3;
                __half2 hA = __floats2half2_rn(p0, p1);
                __half2 hB = __floats2half2_rn(p2, p3);
                pa[q] = *(uint32_t*)&hA;
                pb[q] = *(uint32_t*)&hB;
            }

            if (h == 0) {
                CP_WAIT1();        // V(t) landed (K(t+1) may pend)
                __syncthreads();   // collective visibility of V(t)
            }

            // ---- PV half: 2 k16 groups over this half's 32 keys ----
            #pragma unroll
            for (int ql = 0; ql < 2; ql++) {
                const int kkg = 2 * h + ql;
                uint32_t a[4] = { pa[2 * ql], pb[2 * ql], pa[2 * ql + 1], pb[2 * ql + 1] };
                const int vr = kkg * 16 + l15;
                const int vc = ((lane >> 4) & 1) * 8;
                #pragma unroll
                for (int nh = 0; nh < 4; nh++) {
                    uint32_t bv4[4];
                    ldx4t(bv4, sb + OB_V + SWZ((uint32_t)(vr * 128 + (nh * 16 + vc) * 2)));
                    mma16816(o[2 * nh],     a, bv4);
                    mma16816(o[2 * nh + 1], a, bv4 + 2);
                }
            }
        }
    }

    // ---- epilogue: reduce l across lane%4, normalize, store ----
    l_lo += __shfl_xor_sync(0xffffffffu, l_lo, 1);
    l_lo += __shfl_xor_sync(0xffffffffu, l_lo, 2);
    l_hi += __shfl_xor_sync(0xffffffffu, l_hi, 1);
    l_hi += __shfl_xor_sync(0xffffffffu, l_hi, 2);
    const float inv_lo = 1.0f / l_lo;
    const float inv_hi = 1.0f / l_hi;

    const int r_lo = wid * 16 + (lane >> 2);
    const int r_hi = r_lo + 8;
    #pragma unroll
    for (int nn = 0; nn < 8; nn++) {
        int d0 = nn * 8 + (lane & 3) * 2;
        float2 wlo = { o[nn][0] * inv_lo, o[nn][1] * inv_lo };
        float2 whi = { o[nn][2] * inv_hi, o[nn][3] * inv_hi };
        *(float2*)(Og + (long long)r_lo * DHD + d0) = wlo;
        *(float2*)(Og + (long long)r_hi * DHD + d0) = whi;
    }
}

extern "C" void kernel_launch(void* const* d_in, const int* in_sizes, int n_in,
                              void* d_out, int out_size) {
    const float* Q = (const float*)d_in[0];
    const float* K = (const float*)d_in[1];
    const float* V = (const float*)d_in[2];
    float* O = (float*)d_out;

    const int BH = in_sizes[0] / (S_LEN * DHD);  // 64

    preconv_kernel<<<(unsigned)(TOTE / 8 / 256), 256>>>(K, V);

    cudaFuncSetAttribute(attn_mma_kernel,
                         cudaFuncAttributeMaxDynamicSharedMemorySize, SMEM_BYTES);
    dim3 grid(S_LEN / BM, BH);
    attn_mma_kernel<<<grid, 128, SMEM_BYTES>>>(Q, O);
}